// round 14
// baseline (speedup 1.0000x reference)
#include <cuda_runtime.h>
#include <cstdint>

// Problem constants
#define T_STEPS 512
#define B_TOT   1024
#define IN_DIM  128
#define H_DIM   256
#define OUT_DIM 4
#define BB      7            // batch rows per block (sequential kernel)
#define NBLK_C  147          // ceil(1024/7)
#define NTHR_C  384          // 8 GEMM warps + 4 logits warps (1 per SMSP)

#define HS0_OFF ((size_t)T_STEPS * B_TOT * OUT_DIM)  // 2,097,152

typedef unsigned long long u64;

// ---------------- scratch (no cudaMalloc allowed) -------------------------
__device__ float g_xproj[(size_t)T_STEPS * B_TOT * H_DIM];   // x@Wx^T + b_i2h
__device__ float g_outx [(size_t)T_STEPS * B_TOT * OUT_DIM]; // x@Wox^T + b_i2o

// ---------------- helpers --------------------------------------------------
__device__ __forceinline__ void ffma2(u64& d, u64 a, u64 b) {
    asm("fma.rn.f32x2 %0, %1, %2, %0;" : "+l"(d) : "l"(a), "l"(b));
}
__device__ __forceinline__ u64 pack2(float a, float b) {
    u64 r; asm("mov.b64 %0, {%1, %2};" : "=l"(r) : "f"(a), "f"(b)); return r;
}
__device__ __forceinline__ float hsum2(u64 a) {
    float x, y; asm("mov.b64 {%0,%1}, %2;" : "=f"(x), "=f"(y) : "l"(a));
    return x + y;
}
// fast tanh: tanh(z) = 1 - 2/(exp(2z)+1), via ex2.approx + rcp.approx.
__device__ __forceinline__ float tanh_fast(float z) {
    float e;
    asm("ex2.approx.f32 %0, %1;" : "=f"(e) : "f"(z * 2.8853900817779268f));
    float r;
    asm("rcp.approx.f32 %0, %1;" : "=f"(r) : "f"(e + 1.0f));
    return 1.0f - 2.0f * r;
}

// ===========================================================================
// Kernel A: X_proj = inp @ Wx^T + b_i2h    (unchanged: 977us — at fp32 floor)
// ===========================================================================
#define XT_PAD 132
#define WT_PAD 260
#define A_SMEM_BYTES ((128 * XT_PAD + 128 * WT_PAD) * 4)   // 200,704 B

extern __shared__ float smemA[];

__global__ void __launch_bounds__(512, 1)
xproj_kernel(const float* __restrict__ inp,
             const float* __restrict__ W_i2h,
             const float* __restrict__ b_i2h)
{
    float* sXt = smemA;                   // [k][row]  128 x 132
    float* sWt = smemA + 128 * XT_PAD;    // [k][col]  128 x 260

    const int tid = threadIdx.x;
    const int m0  = blockIdx.x * 128;

    const float4* in4 = (const float4*)inp;
    #pragma unroll
    for (int i = 0; i < 8; ++i) {
        int idx = tid + i * 512;
        int row = idx >> 5, k4 = idx & 31;
        float4 v = in4[(size_t)(m0 + row) * 32 + k4];
        sXt[(k4 * 4 + 0) * XT_PAD + row] = v.x;
        sXt[(k4 * 4 + 1) * XT_PAD + row] = v.y;
        sXt[(k4 * 4 + 2) * XT_PAD + row] = v.z;
        sXt[(k4 * 4 + 3) * XT_PAD + row] = v.w;
    }
    const float4* w4 = (const float4*)W_i2h;
    #pragma unroll
    for (int i = 0; i < 16; ++i) {
        int idx = tid + i * 512;
        int col = idx >> 5, k4 = idx & 31;
        float4 v = w4[(size_t)col * 96 + k4];
        sWt[(k4 * 4 + 0) * WT_PAD + col] = v.x;
        sWt[(k4 * 4 + 1) * WT_PAD + col] = v.y;
        sWt[(k4 * 4 + 2) * WT_PAD + col] = v.z;
        sWt[(k4 * 4 + 3) * WT_PAD + col] = v.w;
    }
    __syncthreads();

    const int warp = tid >> 5;
    const int lane = tid & 31;
    const float* xr = sXt + 8 * warp;
    const float* wc = sWt + 4 * lane;

    u64 acc[8][4];
    {
        float4 b0 = *(const float4*)(b_i2h + 4 * lane);
        float4 b1 = *(const float4*)(b_i2h + 128 + 4 * lane);
        u64 p0 = pack2(b0.x, b0.y), p1 = pack2(b0.z, b0.w);
        u64 p2 = pack2(b1.x, b1.y), p3 = pack2(b1.z, b1.w);
        #pragma unroll
        for (int r = 0; r < 8; ++r) {
            acc[r][0] = p0; acc[r][1] = p1; acc[r][2] = p2; acc[r][3] = p3;
        }
    }

    #pragma unroll 4
    for (int k = 0; k < 128; ++k) {
        float4 a0 = *(const float4*)(xr + (size_t)k * XT_PAD);
        float4 a1 = *(const float4*)(xr + (size_t)k * XT_PAD + 4);
        float4 w0 = *(const float4*)(wc + (size_t)k * WT_PAD);
        float4 w1 = *(const float4*)(wc + (size_t)k * WT_PAD + 128);
        u64 wp0 = pack2(w0.x, w0.y), wp1 = pack2(w0.z, w0.w);
        u64 wp2 = pack2(w1.x, w1.y), wp3 = pack2(w1.z, w1.w);
        float ar[8] = {a0.x, a0.y, a0.z, a0.w, a1.x, a1.y, a1.z, a1.w};
        #pragma unroll
        for (int r = 0; r < 8; ++r) {
            u64 aa = pack2(ar[r], ar[r]);
            ffma2(acc[r][0], wp0, aa);
            ffma2(acc[r][1], wp1, aa);
            ffma2(acc[r][2], wp2, aa);
            ffma2(acc[r][3], wp3, aa);
        }
    }

    float* xp = g_xproj + ((size_t)(m0 + 8 * warp)) * 256 + 4 * lane;
    #pragma unroll
    for (int r = 0; r < 8; ++r) {
        float l0, h0, l1, h1;
        asm("mov.b64 {%0,%1}, %2;" : "=f"(l0), "=f"(h0) : "l"(acc[r][0]));
        asm("mov.b64 {%0,%1}, %2;" : "=f"(l1), "=f"(h1) : "l"(acc[r][1]));
        *(float4*)(xp + (size_t)r * 256) = make_float4(l0, h0, l1, h1);
        asm("mov.b64 {%0,%1}, %2;" : "=f"(l0), "=f"(h0) : "l"(acc[r][2]));
        asm("mov.b64 {%0,%1}, %2;" : "=f"(l1), "=f"(h1) : "l"(acc[r][3]));
        *(float4*)(xp + (size_t)r * 256 + 128) = make_float4(l0, h0, l1, h1);
    }
}

// ===========================================================================
// Kernel B: OutX = inp @ Wo_x^T + b_i2o   (memory-bound)
// ===========================================================================
__global__ void __launch_bounds__(256, 4)
outx_kernel(const float* __restrict__ inp,
            const float* __restrict__ W_i2o,
            const float* __restrict__ b_i2o)
{
    __shared__ float sW[4 * 128];
    __shared__ float sB[4];
    const int tid = threadIdx.x;
    if (tid < 128) {
        #pragma unroll
        for (int o = 0; o < 4; ++o) sW[o * 128 + tid] = W_i2o[o * 384 + tid];
    }
    if (tid < 4) sB[tid] = b_i2o[tid];
    __syncthreads();

    size_t row = (size_t)blockIdx.x * 256 + tid;
    const float4* x4 = (const float4*)inp + row * 32;
    float a0 = sB[0], a1 = sB[1], a2 = sB[2], a3 = sB[3];
    const float4* w0 = (const float4*)sW;
    const float4* w1 = (const float4*)(sW + 128);
    const float4* w2 = (const float4*)(sW + 256);
    const float4* w3 = (const float4*)(sW + 384);
    #pragma unroll 8
    for (int k4 = 0; k4 < 32; ++k4) {
        float4 x = x4[k4];
        float4 v;
        v = w0[k4]; a0 += x.x * v.x + x.y * v.y + x.z * v.z + x.w * v.w;
        v = w1[k4]; a1 += x.x * v.x + x.y * v.y + x.z * v.z + x.w * v.w;
        v = w2[k4]; a2 += x.x * v.x + x.y * v.y + x.z * v.z + x.w * v.w;
        v = w3[k4]; a3 += x.x * v.x + x.y * v.y + x.z * v.z + x.w * v.w;
    }
    *(float4*)&g_outx[row * 4] = make_float4(a0, a1, a2, a3);
}

// ===========================================================================
// Kernel C: sequential recurrence. 147 CTAs x 7 batch rows, 512 steps.
// R14 = R13 (R10 loop + row-split epilogue) with logits work spread over
// 4 warps (8..11), one per SMSP: warp w owns rows {2w, 2w+1} (warp 11: row 6)
// in lanes 0..7. Same sOut/__syncwarp/sQ protocol and arithmetic order.
// ===========================================================================
#define WPAD2 49
#define C_SW_F   (256 * WPAD2 * 4)             // 50176 floats (196 KB)
#define C_SH_F   (C_SW_F)                       // sH  : 1792 f
#define C_SRED_F (C_SH_F + BB * 256)            // sRed: 1792 f
#define C_SWO_F  (C_SRED_F + BB * 256)          // sWo : 1040 f
#define C_SACT_F (C_SWO_F + 4 * 260)            // sAct: 1024 f
#define C_SOUT_F (C_SACT_F + 4 * 256)           // sOut: 32 f
#define C_SQ_F   (C_SOUT_F + 32)                // sQ  : 8 i
#define C_SMEM_BYTES ((C_SQ_F + 8) * 4)         // 223,456 B

extern __shared__ float smemC[];

__global__ void __launch_bounds__(NTHR_C, 1)
rnn_seq_kernel(const float* __restrict__ hidden,
               const float* __restrict__ W_i2h,
               const float* __restrict__ W_i2o,
               const float* __restrict__ actions,
               float* __restrict__ out)
{
    ulonglong2* sW2 = (ulonglong2*)smemC;       // [col][WPAD2]: kh0 slots 0..23, kh1 24..47
    float* sH   = smemC + C_SH_F;
    float* sRed = smemC + C_SRED_F;
    float* sWo  = smemC + C_SWO_F;
    float* sAct = smemC + C_SACT_F;
    float* sOut = smemC + C_SOUT_F;
    int*   sQ   = (int*)(smemC + C_SQ_F);

    const int tid = threadIdx.x;
    const int bs  = blockIdx.x * BB;
    const int rows_cta = min(BB, B_TOT - bs);

    const float4* Wh4 = (const float4*)W_i2h;   // [256 rows][96 f4]; h-part @+32

    const int pr = tid & 127;                   // col-pair index
    const int kh = (tid >> 7) & 1;              // K-half (valid for tid<256)
    const int j0 = pr, j1 = pr + 128;
    const int K4_0 = kh * 32;                   // global k4 base of this half

    // ---- one-time fills ---------------------------------------------------
    if (tid < 256) {
        // smem W: local k4 8..31 of this half, for both cols
        #pragma unroll 6
        for (int j = 8; j < 32; ++j) {
            float4 v0 = Wh4[(size_t)j0 * 96 + 32 + K4_0 + j];
            float4 v1 = Wh4[(size_t)j1 * 96 + 32 + K4_0 + j];
            ulonglong2 p0, p1;
            p0.x = pack2(v0.x, v0.y); p0.y = pack2(v0.z, v0.w);
            p1.x = pack2(v1.x, v1.y); p1.y = pack2(v1.z, v1.w);
            sW2[(size_t)j0 * WPAD2 + kh * 24 + (j - 8)] = p0;
            sW2[(size_t)j1 * WPAD2 + kh * 24 + (j - 8)] = p1;
        }
        if (kh == 0) {
            // initial hidden (cols j0, j1 for all rows)
            #pragma unroll
            for (int r = 0; r < BB; ++r) {
                sH[r * 256 + j0] = (r < rows_cta)
                    ? hidden[(size_t)(bs + r) * 256 + j0] : 0.0f;
                sH[r * 256 + j1] = (r < rows_cta)
                    ? hidden[(size_t)(bs + r) * 256 + j1] : 0.0f;
            }
            #pragma unroll
            for (int i = pr; i < 4 * 256; i += 128) {
                sWo[(i >> 8) * 260 + (i & 255)] =
                    W_i2o[(i >> 8) * 384 + 128 + (i & 255)];
                sAct[i] = actions[i];
            }
        }
    }

    // register W: local k4 0..7 of this half, both cols
    u64 w0lo[8], w0hi[8], w1lo[8], w1hi[8];
    if (tid < 256) {
        #pragma unroll
        for (int j = 0; j < 8; ++j) {
            float4 v0 = Wh4[(size_t)j0 * 96 + 32 + K4_0 + j];
            float4 v1 = Wh4[(size_t)j1 * 96 + 32 + K4_0 + j];
            w0lo[j] = pack2(v0.x, v0.y); w0hi[j] = pack2(v0.z, v0.w);
            w1lo[j] = pack2(v1.x, v1.y); w1hi[j] = pack2(v1.z, v1.w);
        }
    }
    __syncthreads();

    const ulonglong2* sWp0 = sW2 + (size_t)j0 * WPAD2 + kh * 24;
    const ulonglong2* sWp1 = sW2 + (size_t)j1 * WPAD2 + kh * 24;
    const float* hbase = sH + K4_0 * 4;         // this half's h-column window

    // X_proj (carries b_i2h): owned by kh1 threads
    float xp0[BB], xp1[BB];
    int rowg[BB];
    if (tid < 256 && kh == 1) {
        #pragma unroll
        for (int r = 0; r < BB; ++r) rowg[r] = min(bs + r, B_TOT - 1);
        #pragma unroll
        for (int r = 0; r < BB; ++r) {
            xp0[r] = g_xproj[(size_t)rowg[r] * 256 + j0];
            xp1[r] = g_xproj[(size_t)rowg[r] * 256 + j1];
        }
    }

    // ---- logits mapping: warps 8..11 (one per SMSP), 2 rows each in lanes 0..7
    float oxCur = 0.f;
    const int lwarp = (tid >> 5) - 8;               // 0..3 for logits warps
    const int llane = tid & 31;
    const int lr = (lwarp >= 0) ? (lwarp * 2 + (llane >> 2)) : 0;
    const int lo = llane & 3;
    const bool lact = (tid >= 256) && (llane < 8) && (lr < BB) && (lr < rows_cta);
    if (lact) oxCur = g_outx[((size_t)0 * B_TOT + bs + lr) * 4 + lo];

    for (int t = 0; t < T_STEPS; ++t) {
        const int tn = (t + 1 < T_STEPS) ? (t + 1) : t;

        float s0[BB], s1[BB];

        // ---- phase 1: GEMM (K-half partials) + logits warps -----------------
        if (tid < 256) {
            u64 acc0[BB], acc1[BB];
            #pragma unroll
            for (int r = 0; r < BB; ++r) { acc0[r] = 0ull; acc1[r] = 0ull; }

            ulonglong2 bufA[4], bufB[3];
            #pragma unroll
            for (int r = 0; r < 4; ++r)
                bufA[r] = *(const ulonglong2*)(hbase + r * 256);

            #pragma unroll
            for (int j = 0; j < 32; ++j) {
                u64 a0lo, a0hi, a1lo, a1hi;
                if (j < 8) {
                    a0lo = w0lo[j]; a0hi = w0hi[j];
                    a1lo = w1lo[j]; a1hi = w1hi[j];
                } else {
                    ulonglong2 t0 = sWp0[j - 8];
                    ulonglong2 t1 = sWp1[j - 8];
                    a0lo = t0.x; a0hi = t0.y;
                    a1lo = t1.x; a1hi = t1.y;
                }
                // load rows 4..6 of this j
                #pragma unroll
                for (int r = 0; r < 3; ++r)
                    bufB[r] = *(const ulonglong2*)(hbase + (4 + r) * 256 + j * 4);
                // rows 0..3: lo pass then hi pass (acc reuse distance >= 8)
                #pragma unroll
                for (int r = 0; r < 4; ++r) {
                    ffma2(acc0[r], a0lo, bufA[r].x);
                    ffma2(acc1[r], a1lo, bufA[r].x);
                }
                #pragma unroll
                for (int r = 0; r < 4; ++r) {
                    ffma2(acc0[r], a0hi, bufA[r].y);
                    ffma2(acc1[r], a1hi, bufA[r].y);
                }
                // prefetch rows 0..3 of j+1
                if (j < 31) {
                    #pragma unroll
                    for (int r = 0; r < 4; ++r)
                        bufA[r] = *(const ulonglong2*)(hbase + r * 256 + (j + 1) * 4);
                }
                // rows 4..6
                #pragma unroll
                for (int r = 0; r < 3; ++r) {
                    ffma2(acc0[4 + r], a0lo, bufB[r].x);
                    ffma2(acc1[4 + r], a1lo, bufB[r].x);
                }
                #pragma unroll
                for (int r = 0; r < 3; ++r) {
                    ffma2(acc0[4 + r], a0hi, bufB[r].y);
                    ffma2(acc1[4 + r], a1hi, bufB[r].y);
                }
            }

            #pragma unroll
            for (int r = 0; r < BB; ++r) {
                s0[r] = hsum2(acc0[r]);
                s1[r] = hsum2(acc1[r]);
            }

            if (kh == 1) {
                // post partials for rows 0..3 (incl. X_proj/bias; R10 order)
                #pragma unroll
                for (int r = 0; r < 4; ++r) {
                    sRed[r * 256 + j0] = s0[r] + xp0[r];
                    sRed[r * 256 + j1] = s1[r] + xp1[r];
                }
            } else {
                // post partials for rows 4..6
                #pragma unroll
                for (int r = 4; r < BB; ++r) {
                    sRed[r * 256 + j0] = s0[r];
                    sRed[r * 256 + j1] = s1[r];
                }
            }
        } else {
            // ---- logits warps (read old sH; arithmetic order as before) ----
            float acc = 0.f;
            if (lact) {
                const float4* hp = (const float4*)(sH + lr * 256);
                const float4* wp = (const float4*)(sWo + lo * 260);
                float p0 = oxCur, p1 = 0.f, p2 = 0.f, p3 = 0.f;
                #pragma unroll 4
                for (int k4 = 0; k4 < 64; k4 += 4) {
                    float4 h0 = hp[k4],     w0 = wp[k4];
                    float4 h1 = hp[k4 + 1], w1 = wp[k4 + 1];
                    float4 h2 = hp[k4 + 2], w2 = wp[k4 + 2];
                    float4 h3 = hp[k4 + 3], w3 = wp[k4 + 3];
                    p0 += h0.x * w0.x + h0.y * w0.y + h0.z * w0.z + h0.w * w0.w;
                    p1 += h1.x * w1.x + h1.y * w1.y + h1.z * w1.z + h1.w * w1.w;
                    p2 += h2.x * w2.x + h2.y * w2.y + h2.z * w2.z + h2.w * w2.w;
                    p3 += h3.x * w3.x + h3.y * w3.y + h3.z * w3.z + h3.w * w3.w;
                }
                acc = (p0 + p1) + (p2 + p3);
                sOut[lr * 4 + lo] = acc;
            }
            __syncwarp();
            if (lact && lo == 0) {
                float best = sOut[lr * 4]; int q = 0;
                #pragma unroll
                for (int oo = 1; oo < 4; ++oo) {
                    float v = sOut[lr * 4 + oo];
                    if (v > best) { best = v; q = oo; }
                }
                sQ[lr] = q;
            }
            if (lact) {
                out[((size_t)t * B_TOT + bs + lr) * 4 + lo] = acc;
                oxCur = g_outx[((size_t)tn * B_TOT + bs + lr) * 4 + lo];
            }
        }

        __syncthreads();   // B1: partials + sQ ready; all reads of old sH done

        // ---- phase 2: split epilogue ---------------------------------------
        if (tid < 256) {
            if (kh == 0) {
                // finalize rows 0..3 (identical arithmetic to R10)
                #pragma unroll
                for (int r = 0; r < 4; ++r) {
                    if (r < rows_cta) {
                        float z0 = s0[r] + sRed[r * 256 + j0];
                        float z1 = s1[r] + sRed[r * 256 + j1];
                        float h0 = tanh_fast(z0);
                        float h1 = tanh_fast(z1);
                        if (t == 0) {
                            out[HS0_OFF + (size_t)(bs + r) * 256 + j0] = h0;
                            out[HS0_OFF + (size_t)(bs + r) * 256 + j1] = h1;
                        }
                        int q = sQ[r];
                        sH[r * 256 + j0] = h0 * (1.0f + sAct[q * 256 + j0]);
                        sH[r * 256 + j1] = h1 * (1.0f + sAct[q * 256 + j1]);
                    }
                }
            } else {
                // finalize rows 4..6 (kh1 owns xp)
                #pragma unroll
                for (int r = 4; r < BB; ++r) {
                    if (r < rows_cta) {
                        float z0 = (s0[r] + sRed[r * 256 + j0]) + xp0[r];
                        float z1 = (s1[r] + sRed[r * 256 + j1]) + xp1[r];
                        float h0 = tanh_fast(z0);
                        float h1 = tanh_fast(z1);
                        if (t == 0) {
                            out[HS0_OFF + (size_t)(bs + r) * 256 + j0] = h0;
                            out[HS0_OFF + (size_t)(bs + r) * 256 + j1] = h1;
                        }
                        int q = sQ[r];
                        sH[r * 256 + j0] = h0 * (1.0f + sAct[q * 256 + j0]);
                        sH[r * 256 + j1] = h1 * (1.0f + sAct[q * 256 + j1]);
                    }
                }
                // prefetch next step's X_proj (after last use of xp)
                #pragma unroll
                for (int r = 0; r < BB; ++r) {
                    xp0[r] = g_xproj[((size_t)tn * B_TOT + rowg[r]) * 256 + j0];
                    xp1[r] = g_xproj[((size_t)tn * B_TOT + rowg[r]) * 256 + j1];
                }
            }
        }

        __syncthreads();   // B2: new h visible to everyone
    }
}

// ===========================================================================
extern "C" void kernel_launch(void* const* d_in, const int* in_sizes, int n_in,
                              void* d_out, int out_size)
{
    const float* inp     = (const float*)d_in[0];
    const float* hidden  = (const float*)d_in[1];
    const float* W_i2h   = (const float*)d_in[2];
    const float* b_i2h   = (const float*)d_in[3];
    const float* W_i2o   = (const float*)d_in[4];
    const float* b_i2o   = (const float*)d_in[5];
    const float* actions = (const float*)d_in[6];
    float* out = (float*)d_out;

    cudaFuncSetAttribute(xproj_kernel,
                         cudaFuncAttributeMaxDynamicSharedMemorySize, A_SMEM_BYTES);
    cudaFuncSetAttribute(rnn_seq_kernel,
                         cudaFuncAttributeMaxDynamicSharedMemorySize, C_SMEM_BYTES);

    xproj_kernel<<<(T_STEPS * B_TOT) / 128, 512, A_SMEM_BYTES>>>(inp, W_i2h, b_i2h);
    outx_kernel<<<(T_STEPS * B_TOT) / 256, 256>>>(inp, W_i2o, b_i2o);
    rnn_seq_kernel<<<NBLK_C, NTHR_C, C_SMEM_BYTES>>>(hidden, W_i2h, W_i2o,
                                                     actions, out);
}

// round 15
// speedup vs baseline: 1.0922x; 1.0922x over previous
#include <cuda_runtime.h>
#include <cstdint>

// Problem constants
#define T_STEPS 512
#define B_TOT   1024
#define IN_DIM  128
#define H_DIM   256
#define OUT_DIM 4
#define BB      7            // batch rows per block (sequential kernel)
#define NBLK_C  147          // ceil(1024/7)
#define NTHR_C  384          // 8 GEMM warps + 4 K-split logits warps

#define HS0_OFF ((size_t)T_STEPS * B_TOT * OUT_DIM)  // 2,097,152

typedef unsigned long long u64;

// ---------------- scratch (no cudaMalloc allowed) -------------------------
__device__ float g_xproj[(size_t)T_STEPS * B_TOT * H_DIM];   // x@Wx^T + b_i2h
__device__ float g_outx [(size_t)T_STEPS * B_TOT * OUT_DIM]; // x@Wox^T + b_i2o

// ---------------- helpers --------------------------------------------------
__device__ __forceinline__ void ffma2(u64& d, u64 a, u64 b) {
    asm("fma.rn.f32x2 %0, %1, %2, %0;" : "+l"(d) : "l"(a), "l"(b));
}
__device__ __forceinline__ u64 pack2(float a, float b) {
    u64 r; asm("mov.b64 %0, {%1, %2};" : "=l"(r) : "f"(a), "f"(b)); return r;
}
__device__ __forceinline__ float hsum2(u64 a) {
    float x, y; asm("mov.b64 {%0,%1}, %2;" : "=f"(x), "=f"(y) : "l"(a));
    return x + y;
}
// fast tanh: tanh(z) = 1 - 2/(exp(2z)+1), via ex2.approx + rcp.approx.
__device__ __forceinline__ float tanh_fast(float z) {
    float e;
    asm("ex2.approx.f32 %0, %1;" : "=f"(e) : "f"(z * 2.8853900817779268f));
    float r;
    asm("rcp.approx.f32 %0, %1;" : "=f"(r) : "f"(e + 1.0f));
    return 1.0f - 2.0f * r;
}

// ===========================================================================
// Kernel A: X_proj = inp @ Wx^T + b_i2h    (unchanged: 977us — at fp32 floor)
// ===========================================================================
#define XT_PAD 132
#define WT_PAD 260
#define A_SMEM_BYTES ((128 * XT_PAD + 128 * WT_PAD) * 4)   // 200,704 B

extern __shared__ float smemA[];

__global__ void __launch_bounds__(512, 1)
xproj_kernel(const float* __restrict__ inp,
             const float* __restrict__ W_i2h,
             const float* __restrict__ b_i2h)
{
    float* sXt = smemA;                   // [k][row]  128 x 132
    float* sWt = smemA + 128 * XT_PAD;    // [k][col]  128 x 260

    const int tid = threadIdx.x;
    const int m0  = blockIdx.x * 128;

    const float4* in4 = (const float4*)inp;
    #pragma unroll
    for (int i = 0; i < 8; ++i) {
        int idx = tid + i * 512;
        int row = idx >> 5, k4 = idx & 31;
        float4 v = in4[(size_t)(m0 + row) * 32 + k4];
        sXt[(k4 * 4 + 0) * XT_PAD + row] = v.x;
        sXt[(k4 * 4 + 1) * XT_PAD + row] = v.y;
        sXt[(k4 * 4 + 2) * XT_PAD + row] = v.z;
        sXt[(k4 * 4 + 3) * XT_PAD + row] = v.w;
    }
    const float4* w4 = (const float4*)W_i2h;
    #pragma unroll
    for (int i = 0; i < 16; ++i) {
        int idx = tid + i * 512;
        int col = idx >> 5, k4 = idx & 31;
        float4 v = w4[(size_t)col * 96 + k4];
        sWt[(k4 * 4 + 0) * WT_PAD + col] = v.x;
        sWt[(k4 * 4 + 1) * WT_PAD + col] = v.y;
        sWt[(k4 * 4 + 2) * WT_PAD + col] = v.z;
        sWt[(k4 * 4 + 3) * WT_PAD + col] = v.w;
    }
    __syncthreads();

    const int warp = tid >> 5;
    const int lane = tid & 31;
    const float* xr = sXt + 8 * warp;
    const float* wc = sWt + 4 * lane;

    u64 acc[8][4];
    {
        float4 b0 = *(const float4*)(b_i2h + 4 * lane);
        float4 b1 = *(const float4*)(b_i2h + 128 + 4 * lane);
        u64 p0 = pack2(b0.x, b0.y), p1 = pack2(b0.z, b0.w);
        u64 p2 = pack2(b1.x, b1.y), p3 = pack2(b1.z, b1.w);
        #pragma unroll
        for (int r = 0; r < 8; ++r) {
            acc[r][0] = p0; acc[r][1] = p1; acc[r][2] = p2; acc[r][3] = p3;
        }
    }

    #pragma unroll 4
    for (int k = 0; k < 128; ++k) {
        float4 a0 = *(const float4*)(xr + (size_t)k * XT_PAD);
        float4 a1 = *(const float4*)(xr + (size_t)k * XT_PAD + 4);
        float4 w0 = *(const float4*)(wc + (size_t)k * WT_PAD);
        float4 w1 = *(const float4*)(wc + (size_t)k * WT_PAD + 128);
        u64 wp0 = pack2(w0.x, w0.y), wp1 = pack2(w0.z, w0.w);
        u64 wp2 = pack2(w1.x, w1.y), wp3 = pack2(w1.z, w1.w);
        float ar[8] = {a0.x, a0.y, a0.z, a0.w, a1.x, a1.y, a1.z, a1.w};
        #pragma unroll
        for (int r = 0; r < 8; ++r) {
            u64 aa = pack2(ar[r], ar[r]);
            ffma2(acc[r][0], wp0, aa);
            ffma2(acc[r][1], wp1, aa);
            ffma2(acc[r][2], wp2, aa);
            ffma2(acc[r][3], wp3, aa);
        }
    }

    float* xp = g_xproj + ((size_t)(m0 + 8 * warp)) * 256 + 4 * lane;
    #pragma unroll
    for (int r = 0; r < 8; ++r) {
        float l0, h0, l1, h1;
        asm("mov.b64 {%0,%1}, %2;" : "=f"(l0), "=f"(h0) : "l"(acc[r][0]));
        asm("mov.b64 {%0,%1}, %2;" : "=f"(l1), "=f"(h1) : "l"(acc[r][1]));
        *(float4*)(xp + (size_t)r * 256) = make_float4(l0, h0, l1, h1);
        asm("mov.b64 {%0,%1}, %2;" : "=f"(l0), "=f"(h0) : "l"(acc[r][2]));
        asm("mov.b64 {%0,%1}, %2;" : "=f"(l1), "=f"(h1) : "l"(acc[r][3]));
        *(float4*)(xp + (size_t)r * 256 + 128) = make_float4(l0, h0, l1, h1);
    }
}

// ===========================================================================
// Kernel B: OutX = inp @ Wo_x^T + b_i2o   (memory-bound)
// ===========================================================================
__global__ void __launch_bounds__(256, 4)
outx_kernel(const float* __restrict__ inp,
            const float* __restrict__ W_i2o,
            const float* __restrict__ b_i2o)
{
    __shared__ float sW[4 * 128];
    __shared__ float sB[4];
    const int tid = threadIdx.x;
    if (tid < 128) {
        #pragma unroll
        for (int o = 0; o < 4; ++o) sW[o * 128 + tid] = W_i2o[o * 384 + tid];
    }
    if (tid < 4) sB[tid] = b_i2o[tid];
    __syncthreads();

    size_t row = (size_t)blockIdx.x * 256 + tid;
    const float4* x4 = (const float4*)inp + row * 32;
    float a0 = sB[0], a1 = sB[1], a2 = sB[2], a3 = sB[3];
    const float4* w0 = (const float4*)sW;
    const float4* w1 = (const float4*)(sW + 128);
    const float4* w2 = (const float4*)(sW + 256);
    const float4* w3 = (const float4*)(sW + 384);
    #pragma unroll 8
    for (int k4 = 0; k4 < 32; ++k4) {
        float4 x = x4[k4];
        float4 v;
        v = w0[k4]; a0 += x.x * v.x + x.y * v.y + x.z * v.z + x.w * v.w;
        v = w1[k4]; a1 += x.x * v.x + x.y * v.y + x.z * v.z + x.w * v.w;
        v = w2[k4]; a2 += x.x * v.x + x.y * v.y + x.z * v.z + x.w * v.w;
        v = w3[k4]; a3 += x.x * v.x + x.y * v.y + x.z * v.z + x.w * v.w;
    }
    *(float4*)&g_outx[row * 4] = make_float4(a0, a1, a2, a3);
}

// ===========================================================================
// Kernel C: sequential recurrence. 147 CTAs x 7 batch rows, 512 steps.
// R15 = R13 (R10 loop + row-split epilogue) + K-SPLIT logits:
//   warps 8..11 (one per SMSP) each cover 16 k4 of the 64-k4 logits loop
//   with the SAME lane->(row,o) map (28 lanes); partials -> sOut2[4][28];
//   bar.sync(1,128); warp 8 reduces + argmax -> sQ, stores logits.
// ===========================================================================
#define WPAD2 49
#define C_SW_F    (256 * WPAD2 * 4)            // 50176 floats (196 KB)
#define C_SH_F    (C_SW_F)                      // sH   : 1792 f
#define C_SRED_F  (C_SH_F + BB * 256)           // sRed : 1792 f
#define C_SWO_F   (C_SRED_F + BB * 256)         // sWo  : 1040 f
#define C_SACT_F  (C_SWO_F + 4 * 260)           // sAct : 1024 f
#define C_SOUT_F  (C_SACT_F + 4 * 256)          // sOut : 32 f
#define C_SOUT2_F (C_SOUT_F + 32)               // sOut2: 112 f (4 x 28)
#define C_SQ_F    (C_SOUT2_F + 112)             // sQ   : 8 i
#define C_SMEM_BYTES ((C_SQ_F + 8) * 4)         // ~223.9 KB

extern __shared__ float smemC[];

__global__ void __launch_bounds__(NTHR_C, 1)
rnn_seq_kernel(const float* __restrict__ hidden,
               const float* __restrict__ W_i2h,
               const float* __restrict__ W_i2o,
               const float* __restrict__ actions,
               float* __restrict__ out)
{
    ulonglong2* sW2 = (ulonglong2*)smemC;       // [col][WPAD2]: kh0 slots 0..23, kh1 24..47
    float* sH    = smemC + C_SH_F;
    float* sRed  = smemC + C_SRED_F;
    float* sWo   = smemC + C_SWO_F;
    float* sAct  = smemC + C_SACT_F;
    float* sOut  = smemC + C_SOUT_F;
    float* sOut2 = smemC + C_SOUT2_F;
    int*   sQ    = (int*)(smemC + C_SQ_F);

    const int tid = threadIdx.x;
    const int bs  = blockIdx.x * BB;
    const int rows_cta = min(BB, B_TOT - bs);

    const float4* Wh4 = (const float4*)W_i2h;   // [256 rows][96 f4]; h-part @+32

    const int pr = tid & 127;                   // col-pair index
    const int kh = (tid >> 7) & 1;              // K-half (valid for tid<256)
    const int j0 = pr, j1 = pr + 128;
    const int K4_0 = kh * 32;                   // global k4 base of this half

    // ---- one-time fills ---------------------------------------------------
    if (tid < 256) {
        // smem W: local k4 8..31 of this half, for both cols
        #pragma unroll 6
        for (int j = 8; j < 32; ++j) {
            float4 v0 = Wh4[(size_t)j0 * 96 + 32 + K4_0 + j];
            float4 v1 = Wh4[(size_t)j1 * 96 + 32 + K4_0 + j];
            ulonglong2 p0, p1;
            p0.x = pack2(v0.x, v0.y); p0.y = pack2(v0.z, v0.w);
            p1.x = pack2(v1.x, v1.y); p1.y = pack2(v1.z, v1.w);
            sW2[(size_t)j0 * WPAD2 + kh * 24 + (j - 8)] = p0;
            sW2[(size_t)j1 * WPAD2 + kh * 24 + (j - 8)] = p1;
        }
        if (kh == 0) {
            // initial hidden (cols j0, j1 for all rows)
            #pragma unroll
            for (int r = 0; r < BB; ++r) {
                sH[r * 256 + j0] = (r < rows_cta)
                    ? hidden[(size_t)(bs + r) * 256 + j0] : 0.0f;
                sH[r * 256 + j1] = (r < rows_cta)
                    ? hidden[(size_t)(bs + r) * 256 + j1] : 0.0f;
            }
            #pragma unroll
            for (int i = pr; i < 4 * 256; i += 128) {
                sWo[(i >> 8) * 260 + (i & 255)] =
                    W_i2o[(i >> 8) * 384 + 128 + (i & 255)];
                sAct[i] = actions[i];
            }
        }
    }

    // register W: local k4 0..7 of this half, both cols
    u64 w0lo[8], w0hi[8], w1lo[8], w1hi[8];
    if (tid < 256) {
        #pragma unroll
        for (int j = 0; j < 8; ++j) {
            float4 v0 = Wh4[(size_t)j0 * 96 + 32 + K4_0 + j];
            float4 v1 = Wh4[(size_t)j1 * 96 + 32 + K4_0 + j];
            w0lo[j] = pack2(v0.x, v0.y); w0hi[j] = pack2(v0.z, v0.w);
            w1lo[j] = pack2(v1.x, v1.y); w1hi[j] = pack2(v1.z, v1.w);
        }
    }
    __syncthreads();

    const ulonglong2* sWp0 = sW2 + (size_t)j0 * WPAD2 + kh * 24;
    const ulonglong2* sWp1 = sW2 + (size_t)j1 * WPAD2 + kh * 24;
    const float* hbase = sH + K4_0 * 4;         // this half's h-column window

    // X_proj (carries b_i2h): owned by kh1 threads
    float xp0[BB], xp1[BB];
    int rowg[BB];
    if (tid < 256 && kh == 1) {
        #pragma unroll
        for (int r = 0; r < BB; ++r) rowg[r] = min(bs + r, B_TOT - 1);
        #pragma unroll
        for (int r = 0; r < BB; ++r) {
            xp0[r] = g_xproj[(size_t)rowg[r] * 256 + j0];
            xp1[r] = g_xproj[(size_t)rowg[r] * 256 + j1];
        }
    }

    // ---- logits mapping: warps 8..11, K-split (16 k4 each), lanes 0..27
    float oxCur = 0.f;
    const int lwarp = (tid >> 5) - 8;           // 0..3 for logits warps
    const int llane = tid & 31;
    const int lr = llane >> 2;                  // row 0..6 (lanes 0..27)
    const int lo = llane & 3;                   // output 0..3
    const bool lactive = (tid >= 256) && (llane < 28) && (lr < rows_cta);
    if (lactive && lwarp == 0)
        oxCur = g_outx[((size_t)0 * B_TOT + bs + lr) * 4 + lo];

    for (int t = 0; t < T_STEPS; ++t) {
        const int tn = (t + 1 < T_STEPS) ? (t + 1) : t;

        float s0[BB], s1[BB];

        // ---- phase 1: GEMM (K-half partials) + K-split logits ---------------
        if (tid < 256) {
            u64 acc0[BB], acc1[BB];
            #pragma unroll
            for (int r = 0; r < BB; ++r) { acc0[r] = 0ull; acc1[r] = 0ull; }

            ulonglong2 bufA[4], bufB[3];
            #pragma unroll
            for (int r = 0; r < 4; ++r)
                bufA[r] = *(const ulonglong2*)(hbase + r * 256);

            #pragma unroll
            for (int j = 0; j < 32; ++j) {
                u64 a0lo, a0hi, a1lo, a1hi;
                if (j < 8) {
                    a0lo = w0lo[j]; a0hi = w0hi[j];
                    a1lo = w1lo[j]; a1hi = w1hi[j];
                } else {
                    ulonglong2 t0 = sWp0[j - 8];
                    ulonglong2 t1 = sWp1[j - 8];
                    a0lo = t0.x; a0hi = t0.y;
                    a1lo = t1.x; a1hi = t1.y;
                }
                // load rows 4..6 of this j
                #pragma unroll
                for (int r = 0; r < 3; ++r)
                    bufB[r] = *(const ulonglong2*)(hbase + (4 + r) * 256 + j * 4);
                // rows 0..3: lo pass then hi pass (acc reuse distance >= 8)
                #pragma unroll
                for (int r = 0; r < 4; ++r) {
                    ffma2(acc0[r], a0lo, bufA[r].x);
                    ffma2(acc1[r], a1lo, bufA[r].x);
                }
                #pragma unroll
                for (int r = 0; r < 4; ++r) {
                    ffma2(acc0[r], a0hi, bufA[r].y);
                    ffma2(acc1[r], a1hi, bufA[r].y);
                }
                // prefetch rows 0..3 of j+1
                if (j < 31) {
                    #pragma unroll
                    for (int r = 0; r < 4; ++r)
                        bufA[r] = *(const ulonglong2*)(hbase + r * 256 + (j + 1) * 4);
                }
                // rows 4..6
                #pragma unroll
                for (int r = 0; r < 3; ++r) {
                    ffma2(acc0[4 + r], a0lo, bufB[r].x);
                    ffma2(acc1[4 + r], a1lo, bufB[r].x);
                }
                #pragma unroll
                for (int r = 0; r < 3; ++r) {
                    ffma2(acc0[4 + r], a0hi, bufB[r].y);
                    ffma2(acc1[4 + r], a1hi, bufB[r].y);
                }
            }

            #pragma unroll
            for (int r = 0; r < BB; ++r) {
                s0[r] = hsum2(acc0[r]);
                s1[r] = hsum2(acc1[r]);
            }

            if (kh == 1) {
                // post partials for rows 0..3 (incl. X_proj/bias; R10 order)
                #pragma unroll
                for (int r = 0; r < 4; ++r) {
                    sRed[r * 256 + j0] = s0[r] + xp0[r];
                    sRed[r * 256 + j1] = s1[r] + xp1[r];
                }
            } else {
                // post partials for rows 4..6
                #pragma unroll
                for (int r = 4; r < BB; ++r) {
                    sRed[r * 256 + j0] = s0[r];
                    sRed[r * 256 + j1] = s1[r];
                }
            }
        } else {
            // ---- K-split logits: warp lwarp covers k4 [16*lwarp, 16*lwarp+16)
            if (lactive) {
                const float4* hp = (const float4*)(sH + lr * 256);
                const float4* wp = (const float4*)(sWo + lo * 260);
                const int kb = lwarp * 16;
                float p0 = 0.f, p1 = 0.f;
                #pragma unroll
                for (int k4 = 0; k4 < 16; k4 += 2) {
                    float4 h0 = hp[kb + k4],     w0 = wp[kb + k4];
                    float4 h1 = hp[kb + k4 + 1], w1 = wp[kb + k4 + 1];
                    p0 += h0.x * w0.x + h0.y * w0.y + h0.z * w0.z + h0.w * w0.w;
                    p1 += h1.x * w1.x + h1.y * w1.y + h1.z * w1.z + h1.w * w1.w;
                }
                sOut2[lwarp * 28 + llane] = p0 + p1;
            }
            // sync the 4 logits warps (named barrier, 128 threads)
            asm volatile("bar.sync 1, 128;" ::: "memory");

            if (lwarp == 0) {
                float acc = 0.f;
                if (lactive) {
                    acc = ((sOut2[llane] + sOut2[28 + llane]) +
                           (sOut2[56 + llane] + sOut2[84 + llane])) + oxCur;
                    sOut[llane] = acc;
                }
                __syncwarp();
                if (lactive && lo == 0) {
                    float best = sOut[lr * 4]; int q = 0;
                    #pragma unroll
                    for (int oo = 1; oo < 4; ++oo) {
                        float v = sOut[lr * 4 + oo];
                        if (v > best) { best = v; q = oo; }
                    }
                    sQ[lr] = q;
                }
                if (lactive) {
                    out[((size_t)t * B_TOT + bs + lr) * 4 + lo] = acc;
                    oxCur = g_outx[((size_t)tn * B_TOT + bs + lr) * 4 + lo];
                }
            }
        }

        __syncthreads();   // B1: partials + sQ ready; all reads of old sH done

        // ---- phase 2: split epilogue ---------------------------------------
        if (tid < 256) {
            if (kh == 0) {
                // finalize rows 0..3 (identical arithmetic to R10)
                #pragma unroll
                for (int r = 0; r < 4; ++r) {
                    if (r < rows_cta) {
                        float z0 = s0[r] + sRed[r * 256 + j0];
                        float z1 = s1[r] + sRed[r * 256 + j1];
                        float h0 = tanh_fast(z0);
                        float h1 = tanh_fast(z1);
                        if (t == 0) {
                            out[HS0_OFF + (size_t)(bs + r) * 256 + j0] = h0;
                            out[HS0_OFF + (size_t)(bs + r) * 256 + j1] = h1;
                        }
                        int q = sQ[r];
                        sH[r * 256 + j0] = h0 * (1.0f + sAct[q * 256 + j0]);
                        sH[r * 256 + j1] = h1 * (1.0f + sAct[q * 256 + j1]);
                    }
                }
            } else {
                // finalize rows 4..6 (kh1 owns xp)
                #pragma unroll
                for (int r = 4; r < BB; ++r) {
                    if (r < rows_cta) {
                        float z0 = (s0[r] + sRed[r * 256 + j0]) + xp0[r];
                        float z1 = (s1[r] + sRed[r * 256 + j1]) + xp1[r];
                        float h0 = tanh_fast(z0);
                        float h1 = tanh_fast(z1);
                        if (t == 0) {
                            out[HS0_OFF + (size_t)(bs + r) * 256 + j0] = h0;
                            out[HS0_OFF + (size_t)(bs + r) * 256 + j1] = h1;
                        }
                        int q = sQ[r];
                        sH[r * 256 + j0] = h0 * (1.0f + sAct[q * 256 + j0]);
                        sH[r * 256 + j1] = h1 * (1.0f + sAct[q * 256 + j1]);
                    }
                }
                // prefetch next step's X_proj (after last use of xp)
                #pragma unroll
                for (int r = 0; r < BB; ++r) {
                    xp0[r] = g_xproj[((size_t)tn * B_TOT + rowg[r]) * 256 + j0];
                    xp1[r] = g_xproj[((size_t)tn * B_TOT + rowg[r]) * 256 + j1];
                }
            }
        }

        __syncthreads();   // B2: new h visible to everyone
    }
}

// ===========================================================================
extern "C" void kernel_launch(void* const* d_in, const int* in_sizes, int n_in,
                              void* d_out, int out_size)
{
    const float* inp     = (const float*)d_in[0];
    const float* hidden  = (const float*)d_in[1];
    const float* W_i2h   = (const float*)d_in[2];
    const float* b_i2h   = (const float*)d_in[3];
    const float* W_i2o   = (const float*)d_in[4];
    const float* b_i2o   = (const float*)d_in[5];
    const float* actions = (const float*)d_in[6];
    float* out = (float*)d_out;

    cudaFuncSetAttribute(xproj_kernel,
                         cudaFuncAttributeMaxDynamicSharedMemorySize, A_SMEM_BYTES);
    cudaFuncSetAttribute(rnn_seq_kernel,
                         cudaFuncAttributeMaxDynamicSharedMemorySize, C_SMEM_BYTES);

    xproj_kernel<<<(T_STEPS * B_TOT) / 128, 512, A_SMEM_BYTES>>>(inp, W_i2h, b_i2h);
    outx_kernel<<<(T_STEPS * B_TOT) / 256, 256>>>(inp, W_i2o, b_i2o);
    rnn_seq_kernel<<<NBLK_C, NTHR_C, C_SMEM_BYTES>>>(hidden, W_i2h, W_i2o,
                                                     actions, out);
}